// round 1
// baseline (speedup 1.0000x reference)
#include <cuda_runtime.h>
#include <cstdint>

// ============================================================================
// Sparse masked CNN pyramid (14 levels) + MLP head.
// Levels: s_k = 2048,1024,512,256,128,64,32,16,8,4,2,1,1,1  (k = 0..13)
// Level 0: 5x5 conv (cin=1, cout=32) at active pixels of mask.
// Levels 1..13: 3x3 stride-2 conv (32->32) at active cells of downsampled mask.
// Masked global-avg pool per level -> feat[448] -> 256 relu -> 128.
// ============================================================================

#define CAP 131072          // max active cells per level (expected ~42k, 400+ sigma margin)
#define NLEV 14
#define IDX_TOTAL 5592407   // sum of s_k^2 over all 14 levels

// ---------------- device scratch (static; no allocations allowed) -----------
__device__ __align__(16) float g_FA[CAP * 32];   // features, even levels
__device__ __align__(16) float g_FB[CAP * 32];   // features, odd levels
__device__ int   g_idx[IDX_TOTAL];               // dense index maps (all levels)
__device__ int   g_pos[NLEV * CAP];              // compacted active positions (i<<16|j)
__device__ int   g_cnt[NLEV];                    // active counts
__device__ float g_pools[NLEV * 32];             // per-level channel sums

// ---------------- init ------------------------------------------------------
__global__ void init_kernel() {
    int t = threadIdx.x;
    if (t < NLEV) g_cnt[t] = 0;
    if (t < NLEV * 32) g_pools[t] = 0.f;
}

// ---------------- mask pyramid build (block-aggregated compaction) ----------
__global__ void build_kernel(const float* __restrict__ mask, int level, int s,
                             int sprev, int iofs, int iofs_prev) {
    int tid = threadIdx.x;
    int c = blockIdx.x * 1024 + tid;
    int total = s * s;
    bool act = false;
    int i = 0, j = 0;
    if (c < total) {
        i = c / s;
        j = c - i * s;
        if (level == 0) {
            act = (mask[c] != 0.0f);
        } else {
            const int* Ip = g_idx + iofs_prev;
            #pragma unroll
            for (int di = 0; di < 2; di++)
                #pragma unroll
                for (int dj = 0; dj < 2; dj++) {
                    int r = 2 * i + di, cc = 2 * j + dj;
                    if (r < sprev && cc < sprev && Ip[r * sprev + cc] >= 0) act = true;
                }
        }
    }
    unsigned m = __ballot_sync(0xffffffffu, act);
    int wid = tid >> 5, lane = tid & 31;
    __shared__ int wcnt[32];
    __shared__ int wbase[32];
    __shared__ int bbase;
    if (lane == 0) wcnt[wid] = __popc(m);
    __syncthreads();
    if (tid < 32) {
        int cc = wcnt[tid];
        int x = cc;
        #pragma unroll
        for (int o = 1; o < 32; o <<= 1) {
            int y = __shfl_up_sync(0xffffffffu, x, o);
            if (tid >= o) x += y;
        }
        wbase[tid] = x - cc;              // exclusive warp base
        if (tid == 31) bbase = atomicAdd(&g_cnt[level], x);   // one atomic / block
    }
    __syncthreads();
    if (c < total) {
        int idx = -1;
        if (act) {
            idx = bbase + wbase[wid] + __popc(m & ((1u << lane) - 1u));
            if (idx < CAP) g_pos[level * CAP + idx] = (i << 16) | j;
            else idx = -1;                // (unreachable in practice; keeps reads in-bounds)
        }
        g_idx[iofs + c] = idx;
    }
}

// ---------------- level-0 conv: 5x5, cin=1 -> 32, at active pixels ----------
__global__ void conv1_kernel(const float* __restrict__ x, const float* __restrict__ w1) {
    __shared__ float sw[800];
    __shared__ float bsum[32];
    int tid = threadIdx.x;
    for (int t = tid; t < 800; t += 256) sw[t] = w1[t];
    if (tid < 32) bsum[tid] = 0.f;
    __syncthreads();

    int n = min(g_cnt[0], CAP);
    int lane = tid & 31;
    int gw = (blockIdx.x * 256 + tid) >> 5;
    int nw = (gridDim.x * 256) >> 5;
    float pool = 0.f;
    for (int p = gw; p < n; p += nw) {
        int pw = g_pos[p];
        int i = pw >> 16, j = pw & 0xffff;
        float acc = 0.f;
        #pragma unroll
        for (int dy = 0; dy < 5; dy++) {
            int r = i + dy - 2;
            if ((unsigned)r < 2048u) {
                #pragma unroll
                for (int dx = 0; dx < 5; dx++) {
                    int cc = j + dx - 2;
                    if ((unsigned)cc < 2048u)
                        acc = fmaf(x[r * 2048 + cc], sw[(dy * 5 + dx) * 32 + lane], acc);
                }
            }
        }
        acc = fmaxf(acc, 0.f);            // active cell => mask==1, relu only
        g_FA[(size_t)p * 32 + lane] = acc;
        pool += acc;
    }
    atomicAdd(&bsum[lane], pool);
    __syncthreads();
    if (tid < 32) atomicAdd(&g_pools[tid], bsum[tid]);
}

// ---------------- levels 1..13: 3x3 stride-2 conv, 32->32, sparse tile-GEMM -
// Block = 256 threads, tile = 128 positions x 32 channels.
// Dyn smem: sW[9*32*32] + sA[32][128] + sNbr[9][128] + spool[32] = 57984 B
#define CONVK_SMEM 57984

__global__ void convk_kernel(const float* __restrict__ ws, int level, int sprev,
                             int iofs_prev) {
    extern __shared__ float smem[];
    float* sW = smem;                               // 9216 floats
    float* sA = smem + 9216;                        // 4096 floats, layout [ci][p]
    int*   sNbr = (int*)(smem + 9216 + 4096);       // 9*128 ints
    float* spool = (float*)(sNbr + 9 * 128);        // 32 floats

    const float* Fprev;
    float* Fcur;
    if (level & 1) { Fprev = g_FA; Fcur = g_FB; }
    else           { Fprev = g_FB; Fcur = g_FA; }

    int tid = threadIdx.x;
    // load all 9 weight taps for this layer (once per block)
    {
        const float4* wsrc = (const float4*)(ws + (size_t)(level - 1) * 9216);
        float4* wdst = (float4*)sW;
        for (int t = tid; t < 2304; t += 256) wdst[t] = wsrc[t];
    }
    if (tid < 32) spool[tid] = 0.f;
    __syncthreads();

    int n = min(g_cnt[level], CAP);
    const int* posl = g_pos + level * CAP;
    const int* Iprev = g_idx + iofs_prev;

    int ch = (tid & 7) * 4;     // 4 output channels
    int prow = tid >> 3;        // 0..31 position row within tile quarter
    float pl0 = 0.f, pl1 = 0.f, pl2 = 0.f, pl3 = 0.f;

    for (int base = blockIdx.x * 128; base < n; base += gridDim.x * 128) {
        __syncthreads();   // previous tile fully consumed before reusing smem
        // neighbor indices for the 9 taps (threads 0..127, one position each)
        if (tid < 128) {
            int p = base + tid;
            if (p < n) {
                int pw = posl[p];
                int pi = pw >> 16, pj = pw & 0xffff;
                #pragma unroll
                for (int d = 0; d < 9; d++) {
                    int r = 2 * pi + d / 3 - 1;
                    int cc = 2 * pj + d % 3 - 1;
                    int nb = -1;
                    if ((unsigned)r < (unsigned)sprev && (unsigned)cc < (unsigned)sprev)
                        nb = Iprev[r * sprev + cc];
                    sNbr[d * 128 + tid] = nb;
                }
            } else {
                #pragma unroll
                for (int d = 0; d < 9; d++) sNbr[d * 128 + tid] = -1;
            }
        }
        float4 acc[4];
        #pragma unroll
        for (int q = 0; q < 4; q++) acc[q] = make_float4(0.f, 0.f, 0.f, 0.f);

        for (int d = 0; d < 9; d++) {
            // barrier + skip taps with no active neighbor anywhere in the tile
            int any = __syncthreads_or((tid < 128) ? (sNbr[d * 128 + tid] >= 0) : 0);
            if (!any) continue;
            // gather 128 input rows into sA[ci][p] (zeros for inactive)
            {
                int row = tid >> 1;
                int half = tid & 1;
                int cb = half * 16;
                int nb = sNbr[d * 128 + row];
                if (nb >= 0) {
                    const float4* src = (const float4*)(Fprev + (size_t)nb * 32 + cb);
                    #pragma unroll
                    for (int q = 0; q < 4; q++) {
                        float4 v = src[q];
                        int ci = cb + q * 4;
                        sA[(ci + 0) * 128 + row] = v.x;
                        sA[(ci + 1) * 128 + row] = v.y;
                        sA[(ci + 2) * 128 + row] = v.z;
                        sA[(ci + 3) * 128 + row] = v.w;
                    }
                } else {
                    #pragma unroll
                    for (int q = 0; q < 16; q++) sA[(cb + q) * 128 + row] = 0.f;
                }
            }
            __syncthreads();
            // 128x32 += 128x32 * 32x32  (register-blocked 4 pos x 4 ch / thread)
            const float* wd = sW + d * 1024;
            #pragma unroll
            for (int ci = 0; ci < 32; ci++) {
                float4 w = *(const float4*)(wd + ci * 32 + ch);
                float v0 = sA[ci * 128 + prow];
                float v1 = sA[ci * 128 + prow + 32];
                float v2 = sA[ci * 128 + prow + 64];
                float v3 = sA[ci * 128 + prow + 96];
                acc[0].x = fmaf(v0, w.x, acc[0].x); acc[0].y = fmaf(v0, w.y, acc[0].y);
                acc[0].z = fmaf(v0, w.z, acc[0].z); acc[0].w = fmaf(v0, w.w, acc[0].w);
                acc[1].x = fmaf(v1, w.x, acc[1].x); acc[1].y = fmaf(v1, w.y, acc[1].y);
                acc[1].z = fmaf(v1, w.z, acc[1].z); acc[1].w = fmaf(v1, w.w, acc[1].w);
                acc[2].x = fmaf(v2, w.x, acc[2].x); acc[2].y = fmaf(v2, w.y, acc[2].y);
                acc[2].z = fmaf(v2, w.z, acc[2].z); acc[2].w = fmaf(v2, w.w, acc[2].w);
                acc[3].x = fmaf(v3, w.x, acc[3].x); acc[3].y = fmaf(v3, w.y, acc[3].y);
                acc[3].z = fmaf(v3, w.z, acc[3].z); acc[3].w = fmaf(v3, w.w, acc[3].w);
            }
        }
        // epilogue: relu, store, pool partial sums
        #pragma unroll
        for (int q = 0; q < 4; q++) {
            int p = base + prow + 32 * q;
            if (p < n) {
                float4 v;
                v.x = fmaxf(acc[q].x, 0.f);
                v.y = fmaxf(acc[q].y, 0.f);
                v.z = fmaxf(acc[q].z, 0.f);
                v.w = fmaxf(acc[q].w, 0.f);
                *(float4*)(Fcur + (size_t)p * 32 + ch) = v;
                pl0 += v.x; pl1 += v.y; pl2 += v.z; pl3 += v.w;
            }
        }
    }
    // pool reduction: lanes {l, l^8, l^16, l^24} share channels
    pl0 += __shfl_xor_sync(0xffffffffu, pl0, 8); pl0 += __shfl_xor_sync(0xffffffffu, pl0, 16);
    pl1 += __shfl_xor_sync(0xffffffffu, pl1, 8); pl1 += __shfl_xor_sync(0xffffffffu, pl1, 16);
    pl2 += __shfl_xor_sync(0xffffffffu, pl2, 8); pl2 += __shfl_xor_sync(0xffffffffu, pl2, 16);
    pl3 += __shfl_xor_sync(0xffffffffu, pl3, 8); pl3 += __shfl_xor_sync(0xffffffffu, pl3, 16);
    if ((tid & 31) < 8) {
        atomicAdd(&spool[ch + 0], pl0);
        atomicAdd(&spool[ch + 1], pl1);
        atomicAdd(&spool[ch + 2], pl2);
        atomicAdd(&spool[ch + 3], pl3);
    }
    __syncthreads();
    if (tid < 32) atomicAdd(&g_pools[level * 32 + tid], spool[tid]);
}

// ---------------- MLP head: feat[448] -> 256 relu -> 128 --------------------
__global__ void mlp_kernel(const float* __restrict__ wm1, const float* __restrict__ bm1,
                           const float* __restrict__ wm2, const float* __restrict__ bm2,
                           float* __restrict__ out) {
    __shared__ float sf[448];
    __shared__ float sh[256];
    int t = threadIdx.x;
    for (int i = t; i < 448; i += 256) {
        int k = i >> 5;
        float cnt = (float)max(g_cnt[k], 1);
        sf[i] = g_pools[i] / cnt;
    }
    __syncthreads();
    {
        float acc = bm1[t];
        #pragma unroll 4
        for (int i = 0; i < 448; i++) acc = fmaf(sf[i], wm1[i * 256 + t], acc);
        sh[t] = fmaxf(acc, 0.f);
    }
    __syncthreads();
    if (t < 128) {
        float acc = bm2[t];
        #pragma unroll 4
        for (int j = 0; j < 256; j++) acc = fmaf(sh[j], wm2[j * 128 + t], acc);
        out[t] = acc;
    }
}

// ---------------- host launch ------------------------------------------------
static const int LS[NLEV] = {2048, 1024, 512, 256, 128, 64, 32, 16, 8, 4, 2, 1, 1, 1};
static const int IOFS[NLEV] = {
    0, 4194304, 5242880, 5505024, 5570560, 5586944, 5591040,
    5592064, 5592320, 5592384, 5592400, 5592404, 5592405, 5592406};

extern "C" void kernel_launch(void* const* d_in, const int* in_sizes, int n_in,
                              void* d_out, int out_size) {
    const float* x    = (const float*)d_in[0];
    const float* mask = (const float*)d_in[1];
    const float* w1   = (const float*)d_in[2];
    const float* ws   = (const float*)d_in[3];
    const float* wm1  = (const float*)d_in[4];
    const float* bm1  = (const float*)d_in[5];
    const float* wm2  = (const float*)d_in[6];
    const float* bm2  = (const float*)d_in[7];
    float* out = (float*)d_out;

    cudaFuncSetAttribute((const void*)convk_kernel,
                         cudaFuncAttributeMaxDynamicSharedMemorySize, CONVK_SMEM);

    init_kernel<<<1, 512>>>();

    for (int k = 0; k < NLEV; k++) {
        int s = LS[k];
        int sp = k ? LS[k - 1] : 0;
        int cells = s * s;
        int grid = (cells + 1023) / 1024;
        build_kernel<<<grid, 1024>>>(mask, k, s, sp, IOFS[k], k ? IOFS[k - 1] : 0);
    }

    conv1_kernel<<<1024, 256>>>(x, w1);

    for (int k = 1; k < NLEV; k++) {
        convk_kernel<<<444, 256, CONVK_SMEM>>>(ws, k, LS[k - 1], IOFS[k - 1]);
    }

    mlp_kernel<<<1, 256>>>(wm1, bm1, wm2, bm2, out);
}